// round 1
// baseline (speedup 1.0000x reference)
#include <cuda_runtime.h>
#include <cstdint>

// ---------------------------------------------------------------------------
// Runflow: T = 1<<20 time steps.
//   Phase 0 (k0): coalesced read of x (T,9), precompute per-row constants.
//   Phase 1 (k1): pp contraction scan, parallelized via overlapped warmup
//                 (Lipschitz 0.71 per step -> 192-step warmup is exact to fp32).
//   Phase 2 (k3a): elementwise q + shift, store q_shift, block scan aggregates.
//   Phase 3 (k3c): linear-recurrence scan (exact pair composition) + output.
// ---------------------------------------------------------------------------

#define T_TOTAL  (1 << 20)
#define PP_C     128                    // outputs per thread in pp scan
#define PP_W     192                    // warmup steps (0.71^192 ~ 1e-29)
#define PP_NT    (T_TOTAL / PP_C)       // 8192 threads
#define NB       256                    // blocks in scan phase
#define BLK3     256                    // threads per scan block
#define CHUNK    16                     // elements per thread in scan phase
// NB*BLK3*CHUNK == T_TOTAL

// Scratch (device globals: no allocation allowed). float4-typed for 16B align.
__device__ float4 g_D4 [T_TOTAL / 4];   // a*prec - evc
__device__ float4 g_cg4[T_TOTAL / 4];   // greenland*area*(1-f_t)/1000
__device__ float4 g_ci4[T_TOTAL / 4];   // (1.49/n)*sqrt(imp*area)*sqrt(slope)
__device__ float4 g_pre4[T_TOTAL / 4];  // prec_pre (relu'd)
__device__ float4 g_qs4 [T_TOTAL / 4];  // q_shift
__device__ float2 g_bagg[NB];           // per-block scan aggregates (a,b)

// ---------------------------------------------------------------------------
// K0: stage 256 rows of x (9 floats each) through smem (coalesced float4
// loads; smem row stride 9 is coprime with 32 banks -> conflict-free reads),
// emit contiguous precomputed arrays.
// ---------------------------------------------------------------------------
__global__ void k0_prep(const float* __restrict__ x,
                        const float* __restrict__ f0p, const float* __restrict__ fcp,
                        const float* __restrict__ kp,  const float* __restrict__ np,
                        const float* __restrict__ evp, const float* __restrict__ evcp)
{
    __shared__ float tile[256 * 9];
    const int blk = blockIdx.x;
    const float4* src = reinterpret_cast<const float4*>(x) + (size_t)blk * 576;
    float4* t4 = reinterpret_cast<float4*>(tile);
    for (int i = threadIdx.x; i < 576; i += blockDim.x) t4[i] = src[i];
    __syncthreads();

    const float f0 = f0p[0], fc = fcp[0], kk = kp[0], nn = np[0];
    const float a  = 1.0f - evp[0], evc = evcp[0];

    const int r    = threadIdx.x;
    const int base = 9 * r;
    const float gl = tile[base + 0];
    const float im = tile[base + 2];
    const float ar = tile[base + 3];
    const float sl = tile[base + 4];
    const float pr = tile[base + 6];
    const float tp = tile[base + 7];

    const float ft = (f0 - fc) * __expf(-(kk * tp)) + fc;
    const float cg = gl * ar * (1.0f - ft) * 1e-3f;
    const float ci = (1.49f / nn) * sqrtf(im * ar) * sqrtf(sl);
    const float D  = a * pr - evc;

    const int i = blk * 256 + r;
    reinterpret_cast<float*>(g_D4 )[i] = D;
    reinterpret_cast<float*>(g_cg4)[i] = cg;
    reinterpret_cast<float*>(g_ci4)[i] = ci;
}

// One pp step: c' = min/max( a*c + D , a*miss*c + (D + K) ),  K = a*mr*(1-miss)
// (min when the piecewise map is concave, i.e. a*miss <= a; both FMAs are
//  independent -> dependent chain = FFMA + FMNMX ~ 8-9 cycles)
__device__ __forceinline__ float ppstep(float c, float D,
                                        float A1, float A2, float Kc, bool mn)
{
    const float t1 = fmaf(c, A1, D);
    const float t2 = fmaf(c, A2, D + Kc);
    return mn ? fminf(t1, t2) : fmaxf(t1, t2);
}

// ---------------------------------------------------------------------------
// K1: pp scan with overlapped warmup. Thread tid owns outputs [s, s+PP_C),
// s = tid*PP_C. It warms the carry over up to PP_W preceding steps starting
// from guess 0 (exact from pp0 if the warmup window reaches index 0).
// ---------------------------------------------------------------------------
__global__ void k1_ppscan(const float* __restrict__ x,
                          const float* __restrict__ evp, const float* __restrict__ evcp,
                          const float* __restrict__ mrp, const float* __restrict__ missp)
{
    const int tid = blockIdx.x * blockDim.x + threadIdx.x;
    const int s   = tid * PP_C;

    const float a    = 1.0f - evp[0];
    const float miss = missp[0];
    const float mr   = mrp[0];
    const float A1   = a;
    const float A2   = a * miss;
    const float Kc   = a * mr * (1.0f - miss);
    const bool  mn   = (A2 <= A1);
    (void)evcp;  // evc already folded into g_D

    int   jstart = s - PP_W;
    float c;
    if (jstart <= 0) { jstart = 0; c = x[7] - x[6]; }   // exact pp0
    else             { c = 0.0f; }                       // contraction warmup

    // warmup: jstart is a multiple of 4 (s % 128 == 0, PP_W = 192)
    for (int j = jstart; j < s; j += 4) {
        const float4 dv = g_D4[j >> 2];
        c = ppstep(c, dv.x, A1, A2, Kc, mn);
        c = ppstep(c, dv.y, A1, A2, Kc, mn);
        c = ppstep(c, dv.z, A1, A2, Kc, mn);
        c = ppstep(c, dv.w, A1, A2, Kc, mn);
    }

    // main: emit relu(carry) at position j, then advance using D[j]
#pragma unroll 4
    for (int e = 0; e < PP_C; e += 4) {
        const float4 dv = g_D4[(s + e) >> 2];
        float4 o;
        o.x = fmaxf(c, 0.0f); c = ppstep(c, dv.x, A1, A2, Kc, mn);
        o.y = fmaxf(c, 0.0f); c = ppstep(c, dv.y, A1, A2, Kc, mn);
        o.z = fmaxf(c, 0.0f); c = ppstep(c, dv.z, A1, A2, Kc, mn);
        o.w = fmaxf(c, 0.0f); c = ppstep(c, dv.w, A1, A2, Kc, mn);
        g_pre4[(s + e) >> 2] = o;
    }
}

// ---------------------------------------------------------------------------
// K3a: compute q_shift, store it, and produce per-block (a,b) aggregates for
// the linear recurrence h' = wr1*h + wr2*q  (element op = (wr1, wr2*q);
// compose(first,second) = (A1*A2, B1*A2 + B2)). Index 0 contributes s=0.
// ---------------------------------------------------------------------------
__global__ void k3a_q(const float* __restrict__ x,
                      const float* __restrict__ dpp,
                      const float* __restrict__ wr1p, const float* __restrict__ wr2p)
{
    const int blk  = blockIdx.x;
    const int t    = threadIdx.x;
    const int lane = t & 31;
    const int wid  = t >> 5;

    const float dp  = dpp[0];
    const float wr1 = wr1p[0], wr2 = wr2p[0];

    const float rid  = rintf(x[8]);
    const int  shift = (rid == 3723.0f || rid == 870.0f) ? 1 : 4;

    const float* pre = reinterpret_cast<const float*>(g_pre4);
    const float* cg  = reinterpret_cast<const float*>(g_cg4);
    const float* ci  = reinterpret_cast<const float*>(g_ci4);

    const int base = blk * (BLK3 * CHUNK) + t * CHUNK;
    const float e53 = 5.0f / 3.0f;

    float qbuf[CHUNK];
    float A = 1.0f, B = 0.0f;
#pragma unroll
    for (int e = 0; e < CHUNK; ++e) {
        const int gi = base + e;
        const int j  = gi - shift;
        float q = 0.0f;
        if (j >= 0) {
            const float p  = pre[j];
            const float qg = fmaxf(p * cg[j], 0.0f);
            const float d  = fmaxf(p * 1e-3f - dp, 0.0f);
            const float qi = fmaxf(ci[j] * __powf(d, e53), 0.0f);
            q = qg + qi;
        }
        qbuf[e] = q;
        const float sv = (gi == 0) ? 0.0f : wr2 * q;
        B = fmaf(B, wr1, sv);
        A *= wr1;
    }

    float4* qs4 = g_qs4 + (base >> 2);
#pragma unroll
    for (int e = 0; e < CHUNK; e += 4)
        qs4[e >> 2] = make_float4(qbuf[e], qbuf[e + 1], qbuf[e + 2], qbuf[e + 3]);

    // ordered warp reduce (self = earlier segment, neighbor from higher lanes)
#pragma unroll
    for (int d = 1; d < 32; d <<= 1) {
        const float Ao = __shfl_down_sync(0xFFFFFFFFu, A, d);
        const float Bo = __shfl_down_sync(0xFFFFFFFFu, B, d);
        B = fmaf(B, Ao, Bo);
        A *= Ao;
    }
    __shared__ float sWA[8], sWB[8];
    if (lane == 0) { sWA[wid] = A; sWB[wid] = B; }
    __syncthreads();
    if (t == 0) {
        float aa = sWA[0], bb = sWB[0];
#pragma unroll
        for (int w = 1; w < 8; ++w) {
            bb = fmaf(bb, sWA[w], sWB[w]);
            aa *= sWA[w];
        }
        g_bagg[blk] = make_float2(aa, bb);
    }
}

// ---------------------------------------------------------------------------
// K3c: each block scans the 256 block-aggregates (Hillis-Steele in smem) to
// get its own exclusive prefix, redoes the intra-block scan, then emits
//   q2[i] = wz1*h_i + wz2*q_shift[i]  (q2[0] = q_shift[0]);
// if epoch <= 10 the output is just q_shift.
// ---------------------------------------------------------------------------
__global__ void k3c_final(const float* __restrict__ wr1p, const float* __restrict__ wr2p,
                          const float* __restrict__ wz1p, const float* __restrict__ wz2p,
                          const void*  __restrict__ epochp,
                          float* __restrict__ out)
{
    const int blk  = blockIdx.x;
    const int t    = threadIdx.x;
    const int lane = t & 31;
    const int wid  = t >> 5;

    const float wr1 = wr1p[0], wr2 = wr2p[0];
    const float wz1 = wz1p[0], wz2 = wz2p[0];

    // robust epoch read (int32 expected; tolerate float32 encoding)
    int epoch;
    {
        const int iv = *reinterpret_cast<const int*>(epochp);
        if (iv >= 0 && iv < 1000000) epoch = iv;
        else epoch = (int)(*reinterpret_cast<const float*>(epochp));
    }
    const bool pass2 = (epoch > 10);

    __shared__ float sA[NB], sB[NB];
    __shared__ float sWA[8], sWB[8];

    // --- exclusive prefix over block aggregates ---
    {
        const float2 bg = g_bagg[t];
        sA[t] = bg.x; sB[t] = bg.y;
    }
    __syncthreads();
    for (int d = 1; d < NB; d <<= 1) {
        float pa = 1.0f, pb = 0.0f;
        const float ca = sA[t], cb = sB[t];
        if (t >= d) { pa = sA[t - d]; pb = sB[t - d]; }
        __syncthreads();
        sA[t] = pa * ca;
        sB[t] = fmaf(pb, ca, cb);
        __syncthreads();
    }
    float bxA = 1.0f, bxB = 0.0f;
    if (blk > 0) { bxA = sA[blk - 1]; bxB = sB[blk - 1]; }

    // --- reload q_shift, recompute thread-local pair ---
    const int base = blk * (BLK3 * CHUNK) + t * CHUNK;
    float qbuf[CHUNK];
    const float4* qs4 = g_qs4 + (base >> 2);
#pragma unroll
    for (int e = 0; e < CHUNK; e += 4) {
        const float4 v = qs4[e >> 2];
        qbuf[e] = v.x; qbuf[e + 1] = v.y; qbuf[e + 2] = v.z; qbuf[e + 3] = v.w;
    }
    float A = 1.0f, B = 0.0f;
#pragma unroll
    for (int e = 0; e < CHUNK; ++e) {
        const int gi = base + e;
        const float sv = (gi == 0) ? 0.0f : wr2 * qbuf[e];
        B = fmaf(B, wr1, sv);
        A *= wr1;
    }

    // --- inclusive warp scan of pairs ---
#pragma unroll
    for (int d = 1; d < 32; d <<= 1) {
        const float pa = __shfl_up_sync(0xFFFFFFFFu, A, d);
        const float pb = __shfl_up_sync(0xFFFFFFFFu, B, d);
        if (lane >= d) { B = fmaf(pb, A, B); A *= pa; }
    }
    // exclusive-within-warp
    float eA = __shfl_up_sync(0xFFFFFFFFu, A, 1);
    float eB = __shfl_up_sync(0xFFFFFFFFu, B, 1);
    if (lane == 0) { eA = 1.0f; eB = 0.0f; }
    if (lane == 31) { sWA[wid] = A; sWB[wid] = B; }
    __syncthreads();
    if (t == 0) {  // warp aggregates -> warp exclusive prefixes
        float aa = 1.0f, bb = 0.0f;
#pragma unroll
        for (int w = 0; w < 8; ++w) {
            const float ta = sWA[w], tb = sWB[w];
            sWA[w] = aa; sWB[w] = bb;
            bb = fmaf(bb, ta, tb);
            aa *= ta;
        }
    }
    __syncthreads();

    // combined exclusive prefix: blockExcl o warpExcl o threadExcl ; h_in = B
    const float wA = sWA[wid], wB = sWB[wid];
    const float c1A = bxA * wA;
    const float c1B = fmaf(bxB, wA, wB);
    float h = fmaf(c1B, eA, eB);
    (void)c1A;

    float obuf[CHUNK];
#pragma unroll
    for (int e = 0; e < CHUNK; ++e) {
        const int gi = base + e;
        const float q  = qbuf[e];
        const float sv = (gi == 0) ? 0.0f : wr2 * q;
        h = fmaf(h, wr1, sv);
        float o = fmaf(h, wz1, wz2 * q);
        if (gi == 0) o = q;
        obuf[e] = pass2 ? o : q;
    }
    float4* o4 = reinterpret_cast<float4*>(out) + (base >> 2);
#pragma unroll
    for (int e = 0; e < CHUNK; e += 4)
        o4[e >> 2] = make_float4(obuf[e], obuf[e + 1], obuf[e + 2], obuf[e + 3]);
}

// ---------------------------------------------------------------------------
// kernel_launch
// Inputs: 0:x 1:f_0 2:f_c 3:k 4:n 5:d_p 6:evap 7:evap_constant
//         8:missing_restrict 9:missing 10:w_r_1 11:w_r_2 12:w_z_1 13:w_z_2
//         14:epoch
// ---------------------------------------------------------------------------
extern "C" void kernel_launch(void* const* d_in, const int* in_sizes, int n_in,
                              void* d_out, int out_size)
{
    (void)in_sizes; (void)n_in; (void)out_size;
    const float* x    = (const float*)d_in[0];
    const float* f0p  = (const float*)d_in[1];
    const float* fcp  = (const float*)d_in[2];
    const float* kp   = (const float*)d_in[3];
    const float* np   = (const float*)d_in[4];
    const float* dpp  = (const float*)d_in[5];
    const float* evp  = (const float*)d_in[6];
    const float* evcp = (const float*)d_in[7];
    const float* mrp  = (const float*)d_in[8];
    const float* missp= (const float*)d_in[9];
    const float* wr1p = (const float*)d_in[10];
    const float* wr2p = (const float*)d_in[11];
    const float* wz1p = (const float*)d_in[12];
    const float* wz2p = (const float*)d_in[13];
    const void*  epochp = d_in[14];
    float* out = (float*)d_out;

    k0_prep  <<<T_TOTAL / 256, 256>>>(x, f0p, fcp, kp, np, evp, evcp);
    k1_ppscan<<<PP_NT / 32, 32>>>(x, evp, evcp, mrp, missp);
    k3a_q    <<<NB, BLK3>>>(x, dpp, wr1p, wr2p);
    k3c_final<<<NB, BLK3>>>(wr1p, wr2p, wz1p, wz2p, epochp, out);
}